// round 17
// baseline (speedup 1.0000x reference)
#include <cuda_runtime.h>
#include <cstdint>

// CBModel: output = concat(gen_poses [2,32,18,256,256], step_poses [2,32,18,256,256]) fp32
//   = 604 MB zeros + <=2304 one-hot 1.0 elements.
//
// Champion structure (R6/R16 = 86.0us), swept exhaustively R4-R16:
//   - driver memset = 7.37 TB/s = the DRAM write ceiling (parallel memsets
//     don't scale; STG.wb 6.8 / TMA S2G 6.6 / STG.cs 5.7 all slower).
//   - one memset node + ONE fused trailing kernel is optimal.
// This round's single tweak: tail-fill granularity 4 -> 8 blocks/plane
// (64KB -> 32KB per block), halving the slowest block's fill time inside the
// trailing kernel while staying far under one wave (265 blocks).

static constexpr int BC      = 32 * 18;    // 576
static constexpr int C_KP    = 18;
static constexpr int HW      = 256 * 256;  // 65536 floats per plane
static constexpr int PLANES  = 4 * BC;     // 2304

static constexpr int TAIL_PLANES      = 32;
static constexpr int HEAD_PLANES      = PLANES - TAIL_PLANES;   // 2272
static constexpr int BLOCKS_PER_PLANE = 8;
static constexpr int PIECE            = HW / BLOCKS_PER_PLANE;  // 8192 floats (32KB)
static constexpr int FILL_BLOCKS      = TAIL_PLANES * BLOCKS_PER_PLANE; // 256
static constexpr int ONES_BLOCKS      = (HEAD_PLANES + 255) / 256;      // 9
static constexpr int GRID             = FILL_BLOCKS + ONES_BLOCKS;      // 265

// Hot index for a plane: -1 if out of bounds, else x*256+y.
// Bit-exact to the reference: jnp.trunc+int32 == C trunc-toward-zero cast;
// floor_divide via floorf((b-a)/3); step coords accumulated sequentially
// (p1+st, then +st again) to reproduce the reference's two float roundings.
__device__ __forceinline__ int plane_hot(int plane,
                                         const float* __restrict__ pose1,
                                         const float* __restrict__ pose2)
{
    float cx, cy;
    if (plane < 2 * BC) {
        // gen half: sample-0 coords, replicated over batch
        const int k   = plane / BC;            // 0 -> pose1, 1 -> pose2
        const int rem = plane - k * BC;
        const int c   = rem % C_KP;
        const float* P = k ? pose2 : pose1;
        cx = P[2 * c];
        cy = P[2 * c + 1];
    } else {
        const int q   = plane - 2 * BC;
        const int s   = q / BC;                // 0 -> one step, 1 -> two steps
        const int rem = q - s * BC;            // rem = b*18 + c
        const float ax = pose1[2 * rem],  ay = pose1[2 * rem + 1];
        const float bx = pose2[2 * rem],  by = pose2[2 * rem + 1];
        const float sx = floorf((bx - ax) / 3.0f);
        const float sy = floorf((by - ay) / 3.0f);
        cx = ax + sx;  cy = ay + sy;
        if (s == 1) { cx += sx; cy += sy; }
    }
    const int x = (int)cx;
    const int y = (int)cy;
    const bool valid = (x >= 0) & (x <= 255) & (y >= 0) & (y <= 255);
    return valid ? ((x << 8) | y) : -1;
}

__global__ __launch_bounds__(256)
void cbmodel_fused_tail_kernel(const float* __restrict__ pose1,
                               const float* __restrict__ pose2,
                               float* __restrict__ out)
{
    const int b = blockIdx.x;

    if (b < FILL_BLOCKS) {
        // ---- tail fill: block b covers piece (b%8) of plane HEAD+(b/8) ----
        const int plane = HEAD_PLANES + (b / BLOCKS_PER_PLANE);
        const int q     = b % BLOCKS_PER_PLANE;
        const int hot   = plane_hot(plane, pose1, pose2);

        float* base = out + (size_t)plane * HW + (size_t)q * PIECE;
        float4* __restrict__ dst = reinterpret_cast<float4*>(base);
        const float4 z = make_float4(0.0f, 0.0f, 0.0f, 0.0f);
        #pragma unroll
        for (int i = threadIdx.x; i < PIECE / 4; i += 256) {
            dst[i] = z;
        }

        __syncthreads();
        const int lo = q * PIECE;
        if (threadIdx.x == 0 && hot >= lo && hot < lo + PIECE) {
            out[(size_t)plane * HW + hot] = 1.0f;
        }
    } else {
        // ---- head ones: one thread per head plane (memset zeroed the head) ----
        const int plane = (b - FILL_BLOCKS) * 256 + threadIdx.x;
        if (plane < HEAD_PLANES) {
            const int hot = plane_hot(plane, pose1, pose2);
            if (hot >= 0) {
                out[(size_t)plane * HW + hot] = 1.0f;
            }
        }
    }
}

extern "C" void kernel_launch(void* const* d_in, const int* in_sizes, int n_in,
                              void* d_out, int out_size)
{
    const float* pose1 = (const float*)d_in[0];   // [32,18,2] float32
    const float* pose2 = (const float*)d_in[1];   // [32,18,2] float32
    float* out = (float*)d_out;

    (void)in_sizes; (void)n_in; (void)out_size;

    // Bulk zero of the head planes via the driver memset path (~7.37 TB/s,
    // the measured DRAM write ceiling).
    cudaMemsetAsync(out, 0, (size_t)HEAD_PLANES * HW * sizeof(float), 0);

    // Fused trailing kernel: tail fill + tail ones + head ones.
    cbmodel_fused_tail_kernel<<<GRID, 256>>>(pose1, pose2, out);
}